// round 1
// baseline (speedup 1.0000x reference)
#include <cuda_runtime.h>

// Neural CA step, fused: depthwise perception (3x3, K=3) -> [48->128 relu] ->
// [128->16] -> residual + clip.  fp32 baseline, register-tiled GEMMs.
//
// Shapes: x [8,512,512,16], perc [3,3,3], W1 [48,128], b1[128], W2 [128,16],
// b2[16], out [8,512,512,16].

#define Bb   8
#define Hh   512
#define Wd   512
#define Cc   16
#define CK   48
#define HID  128
#define MT   64     // pixels per block (strip along w)
#define STP  68     // S-tile row pitch (floats), padded

__global__ __launch_bounds__(256, 3)
void nca_step_kernel(const float* __restrict__ x,
                     const float* __restrict__ perc,
                     const float* __restrict__ W1,
                     const float* __restrict__ b1,
                     const float* __restrict__ W2,
                     const float* __restrict__ b2,
                     float* __restrict__ out)
{
    // Static shared: W1s 24KB + W2t 8KB + St 13.06KB + small = ~45.8KB
    __shared__ float W1s[CK * HID];        // [k][d] row-major (same as global)
    __shared__ float W2t[Cc * HID];        // transposed: [o][d]
    __shared__ float St [CK * STP];        // [k][m] perception output (fp32)
    __shared__ float b1s[HID];
    __shared__ float b2s[Cc];
    __shared__ float pcs[28];              // 27 perception weights
    // dxs aliases the front of St (St no longer needed once GEMM1 is done;
    // a __syncthreads separates the phases).
    float* dxs = St;                       // [m][o] : 64*16 floats

    const int tid = threadIdx.x;
    const int w0  = blockIdx.x * MT;
    const int hh  = blockIdx.y;
    const int bb  = blockIdx.z;

    // ---- cooperative weight loads ----
    for (int u = tid; u < CK * HID / 4; u += 256)
        ((float4*)W1s)[u] = ((const float4*)W1)[u];
    for (int u = tid; u < HID * Cc; u += 256) {
        int d = u >> 4, o = u & 15;
        W2t[o * HID + d] = W2[u];
    }
    if (tid < HID) b1s[tid] = b1[tid];
    if (tid < Cc)  b2s[tid] = b2[tid];
    if (tid < 27)  pcs[tid] = perc[tid];
    __syncthreads();

    // ---- perception: St[c*3+kk][m] = sum_{r,j} perc[r][j][kk] * x[h+r-1][w+m+j-1][c]
    // 1024 (c,m) pairs, 4 per thread; x read straight from global (L1-resident strip).
    #pragma unroll
    for (int pp = 0; pp < 4; pp++) {
        int pidx = tid + pp * 256;
        int c = pidx & 15;
        int m = pidx >> 4;
        float xv[3][3];
        #pragma unroll
        for (int r = 0; r < 3; r++) {
            int gh = hh + r - 1;
            #pragma unroll
            for (int j = 0; j < 3; j++) {
                int gw = w0 + m + j - 1;
                float v = 0.f;
                if (gh >= 0 && gh < Hh && gw >= 0 && gw < Wd)
                    v = x[(((size_t)bb * Hh + gh) * Wd + gw) * Cc + c];
                xv[r][j] = v;
            }
        }
        #pragma unroll
        for (int kk = 0; kk < 3; kk++) {
            float s = 0.f;
            #pragma unroll
            for (int r = 0; r < 3; r++)
                #pragma unroll
                for (int j = 0; j < 3; j++)
                    s += pcs[(r * 3 + j) * 3 + kk] * xv[r][j];
            St[(c * 3 + kk) * STP + m] = s;
        }
    }
    __syncthreads();

    // ---- GEMM1: H[64 x 128] = S[64 x 48] @ W1[48 x 128], +b1, relu ----
    // thread (tm, td): tm = tid>>4 owns m rows tm*4..tm*4+3; td = tid&15 owns
    // d cols td*8..td*8+7.  Warp = {2 tm values} x {16 td values} -> the d
    // reduction in GEMM2 is a 16-lane shfl_xor.
    const int td = tid & 15;
    const int tm = tid >> 4;

    float acc[4][8];
    #pragma unroll
    for (int i = 0; i < 4; i++)
        #pragma unroll
        for (int j = 0; j < 8; j++)
            acc[i][j] = b1s[td * 8 + j];

    #pragma unroll 8
    for (int k = 0; k < CK; k++) {
        float4 a  = *(const float4*)(St  + k * STP + tm * 4);
        float4 u4 = *(const float4*)(W1s + k * HID + td * 8);
        float4 v4 = *(const float4*)(W1s + k * HID + td * 8 + 4);
        float av[4] = {a.x, a.y, a.z, a.w};
        float bv[8] = {u4.x, u4.y, u4.z, u4.w, v4.x, v4.y, v4.z, v4.w};
        #pragma unroll
        for (int i = 0; i < 4; i++)
            #pragma unroll
            for (int j = 0; j < 8; j++)
                acc[i][j] += av[i] * bv[j];
    }
    #pragma unroll
    for (int i = 0; i < 4; i++)
        #pragma unroll
        for (int j = 0; j < 8; j++)
            acc[i][j] = fmaxf(acc[i][j], 0.f);

    __syncthreads();   // St reads done everywhere; dxs (aliased) now writable

    // ---- GEMM2: dx[64 x 16] = H @ W2[128 x 16]; reduce partials over td ----
    for (int o = 0; o < Cc; o++) {
        float4 u4 = *(const float4*)(W2t + o * HID + td * 8);
        float4 v4 = *(const float4*)(W2t + o * HID + td * 8 + 4);
        float wv[8] = {u4.x, u4.y, u4.z, u4.w, v4.x, v4.y, v4.z, v4.w};
        float p[4] = {0.f, 0.f, 0.f, 0.f};
        #pragma unroll
        for (int i = 0; i < 4; i++)
            #pragma unroll
            for (int j = 0; j < 8; j++)
                p[i] += acc[i][j] * wv[j];
        // reduce over the 16 td lanes (xor < 16 stays within the half-warp,
        // which shares tm)
        #pragma unroll
        for (int s = 1; s < 16; s <<= 1) {
            #pragma unroll
            for (int i = 0; i < 4; i++)
                p[i] += __shfl_xor_sync(0xffffffffu, p[i], s);
        }
        if (td == o) {
            #pragma unroll
            for (int i = 0; i < 4; i++)
                dxs[(tm * 4 + i) * Cc + o] = p[i];
        }
    }
    __syncthreads();

    // ---- epilogue: out = clip(x + dx + b2, 0, 1), coalesced float4 ----
    {
        int m = tid >> 2;
        int g = tid & 3;
        size_t gidx = (((size_t)bb * Hh + hh) * Wd + w0 + m) * Cc + g * 4;
        float4 dv = *(const float4*)(dxs + m * Cc + g * 4);
        float4 xc = *(const float4*)(x + gidx);
        float4 bv = *(const float4*)(b2s + g * 4);
        float4 r;
        r.x = fminf(fmaxf(xc.x + dv.x + bv.x, 0.f), 1.f);
        r.y = fminf(fmaxf(xc.y + dv.y + bv.y, 0.f), 1.f);
        r.z = fminf(fmaxf(xc.z + dv.z + bv.z, 0.f), 1.f);
        r.w = fminf(fmaxf(xc.w + dv.w + bv.w, 0.f), 1.f);
        *(float4*)(out + gidx) = r;
    }
}

extern "C" void kernel_launch(void* const* d_in, const int* in_sizes, int n_in,
                              void* d_out, int out_size)
{
    const float* x    = (const float*)d_in[0];
    const float* perc = (const float*)d_in[1];
    const float* W1   = (const float*)d_in[2];
    const float* b1   = (const float*)d_in[3];
    const float* W2   = (const float*)d_in[4];
    const float* b2   = (const float*)d_in[5];
    // d_in[6] = lock_release (unused)
    float* out = (float*)d_out;
    (void)in_sizes; (void)n_in; (void)out_size;

    dim3 grid(Wd / MT, Hh, Bb);   // (8, 512, 8)
    nca_step_kernel<<<grid, 256>>>(x, perc, W1, b1, W2, b2, out);
}

// round 4
// speedup vs baseline: 5.3172x; 5.3172x over previous
#include <cuda_runtime.h>
#include <cuda_fp16.h>
#include <cstdint>

// Neural CA step via legacy mma.sync (fp16 x fp16 -> f32), no tcgen05 (the
// harness targets compute_103 without the 'a' feature set).
// x[8,512,512,16] -> perception[48] -> [48->128 relu] -> [128->16] -> +x, clip.

#define Bb 8
#define Hh 512
#define Wd 512
#define Cc 16
#define CK 48          // C*K perception channels
#define HID 128
#define MT 128         // pixels per CTA
#define NT 256         // 8 warps

#define SP 56          // S row pitch in halves (conflict-free fragment loads)
#define W1P 56         // W1t row pitch in halves
#define W2P 136        // W2t row pitch in halves

__device__ __forceinline__ uint32_t h2u(__half2 h) {
    uint32_t u;
    __builtin_memcpy(&u, &h, 4);
    return u;
}

__device__ __forceinline__ void mma16816(float& c0, float& c1, float& c2, float& c3,
                                         uint32_t a0, uint32_t a1, uint32_t a2, uint32_t a3,
                                         uint32_t b0, uint32_t b1)
{
    asm volatile(
        "mma.sync.aligned.m16n8k16.row.col.f32.f16.f16.f32 "
        "{%0,%1,%2,%3}, {%4,%5,%6,%7}, {%8,%9}, {%0,%1,%2,%3};"
        : "+f"(c0), "+f"(c1), "+f"(c2), "+f"(c3)
        : "r"(a0), "r"(a1), "r"(a2), "r"(a3), "r"(b0), "r"(b1));
}

__global__ __launch_bounds__(NT, 2)
void nca_mma_kernel(const float* __restrict__ x,
                    const float* __restrict__ perc,
                    const float* __restrict__ W1,
                    const float* __restrict__ b1,
                    const float* __restrict__ W2,
                    const float* __restrict__ b2,
                    float* __restrict__ out)
{
    __shared__ __half S  [MT * SP];     // perception output [m][k]   14.0 KB
    __shared__ __half W1t[HID * W1P];   // W1^T [n][k]                14.0 KB
    __shared__ __half W2t[Cc * W2P];    // W2^T [n][k]                 4.3 KB
    __shared__ float  b1s[HID];
    __shared__ float  b2s[Cc];
    __shared__ float  pcs[28];

    const int tid = threadIdx.x;
    const int wid = tid >> 5;
    const int lid = tid & 31;
    const int gid = lid >> 2;          // 0..7  (m16n8 "groupID")
    const int tg  = lid & 3;           // 0..3  (threadID_in_group)
    const int w0  = blockIdx.x * MT;
    const int hh  = blockIdx.y;
    const int bb  = blockIdx.z;

    // ---- stage weights ----
    for (int u = tid; u < CK * HID; u += NT) {          // W1 [k][n] -> W1t[n][k]
        int k = u >> 7, n = u & 127;
        W1t[n * W1P + k] = __float2half_rn(W1[u]);
    }
    for (int u = tid; u < HID * Cc; u += NT) {          // W2 [k][n] -> W2t[n][k]
        int k = u >> 4, n = u & 15;
        W2t[n * W2P + k] = __float2half_rn(W2[u]);
    }
    if (tid < HID) b1s[tid] = b1[tid];
    if (tid < Cc)  b2s[tid] = b2[tid];
    if (tid < 27)  pcs[tid] = perc[tid];
    __syncthreads();

    // ---- perception: S[m][c*3+kk] fp16; 2 items/thread, item=(m, channel-group) ----
    #pragma unroll
    for (int it = 0; it < 2; ++it) {
        int item = tid + it * NT;
        int m = item >> 2, cg = item & 3;
        float4 a0 = {0,0,0,0}, a1 = {0,0,0,0}, a2 = {0,0,0,0};
        #pragma unroll
        for (int r = 0; r < 3; r++) {
            int gh = hh + r - 1;
            bool okh = (gh >= 0) && (gh < Hh);
            #pragma unroll
            for (int j = 0; j < 3; j++) {
                int gw = w0 + m + j - 1;
                float4 xv = {0,0,0,0};
                if (okh && gw >= 0 && gw < Wd)
                    xv = *(const float4*)(x + ((((size_t)bb * Hh + gh) * Wd + gw) << 4) + cg * 4);
                float p0 = pcs[(r*3+j)*3 + 0];
                float p1 = pcs[(r*3+j)*3 + 1];
                float p2 = pcs[(r*3+j)*3 + 2];
                a0.x += p0*xv.x; a0.y += p0*xv.y; a0.z += p0*xv.z; a0.w += p0*xv.w;
                a1.x += p1*xv.x; a1.y += p1*xv.y; a1.z += p1*xv.z; a1.w += p1*xv.w;
                a2.x += p2*xv.x; a2.y += p2*xv.y; a2.z += p2*xv.z; a2.w += p2*xv.w;
            }
        }
        // k = c*3+kk, c = cg*4..cg*4+3  ->  12 consecutive k starting at cg*12
        float v[12] = {a0.x, a1.x, a2.x,  a0.y, a1.y, a2.y,
                       a0.z, a1.z, a2.z,  a0.w, a1.w, a2.w};
        __half2* dst = (__half2*)(S + m * SP + cg * 12);
        #pragma unroll
        for (int q = 0; q < 6; q++)
            dst[q] = __floats2half2_rn(v[2*q], v[2*q+1]);
    }
    __syncthreads();

    // ---- GEMM1: H[16 x 128] per warp = S_tile[16 x 48] @ W1 ----
    const int m0 = wid * 16;

    uint32_t af[3][4];   // A fragments for 3 K-steps, cached
    #pragma unroll
    for (int s = 0; s < 3; s++) {
        const __half* base = S + s * 16 + tg * 2;
        af[s][0] = *(const uint32_t*)(base + (m0 + gid)     * SP);
        af[s][1] = *(const uint32_t*)(base + (m0 + gid + 8) * SP);
        af[s][2] = *(const uint32_t*)(base + (m0 + gid)     * SP + 8);
        af[s][3] = *(const uint32_t*)(base + (m0 + gid + 8) * SP + 8);
    }

    float acc[16][4];
    #pragma unroll
    for (int j = 0; j < 16; j++)
        acc[j][0] = acc[j][1] = acc[j][2] = acc[j][3] = 0.f;

    #pragma unroll
    for (int j = 0; j < 16; j++) {
        const __half* bb1 = W1t + (j * 8 + gid) * W1P + tg * 2;
        #pragma unroll
        for (int s = 0; s < 3; s++) {
            uint32_t b0 = *(const uint32_t*)(bb1 + s * 16);
            uint32_t b1r = *(const uint32_t*)(bb1 + s * 16 + 8);
            mma16816(acc[j][0], acc[j][1], acc[j][2], acc[j][3],
                     af[s][0], af[s][1], af[s][2], af[s][3], b0, b1r);
        }
    }

    // ---- +b1, relu, convert C-frags -> A-frags (registers only) ----
    uint32_t hA[8][4];
    #pragma unroll
    for (int j = 0; j < 16; j++) {
        float2 bj = *(const float2*)(b1s + j * 8 + tg * 2);
        float c0 = fmaxf(acc[j][0] + bj.x, 0.f);
        float c1 = fmaxf(acc[j][1] + bj.y, 0.f);
        float c2 = fmaxf(acc[j][2] + bj.x, 0.f);
        float c3 = fmaxf(acc[j][3] + bj.y, 0.f);
        uint32_t lo = h2u(__floats2half2_rn(c0, c1));
        uint32_t hi = h2u(__floats2half2_rn(c2, c3));
        hA[j >> 1][(j & 1) ? 2 : 0] = lo;
        hA[j >> 1][(j & 1) ? 3 : 1] = hi;
    }

    // ---- GEMM2: dx[16 x 16] per warp = H @ W2 ----
    float acc2[2][4];
    acc2[0][0] = acc2[0][1] = acc2[0][2] = acc2[0][3] = 0.f;
    acc2[1][0] = acc2[1][1] = acc2[1][2] = acc2[1][3] = 0.f;
    #pragma unroll
    for (int jc = 0; jc < 2; jc++) {
        const __half* bb2 = W2t + (jc * 8 + gid) * W2P + tg * 2;
        #pragma unroll
        for (int s = 0; s < 8; s++) {
            uint32_t b0 = *(const uint32_t*)(bb2 + s * 16);
            uint32_t b1r = *(const uint32_t*)(bb2 + s * 16 + 8);
            mma16816(acc2[jc][0], acc2[jc][1], acc2[jc][2], acc2[jc][3],
                     hA[s][0], hA[s][1], hA[s][2], hA[s][3], b0, b1r);
        }
    }

    // ---- epilogue: out = clip(x + dx + b2, 0, 1); C-frag direct stores ----
    #pragma unroll
    for (int half_ = 0; half_ < 2; half_++) {           // row and row+8
        int m = m0 + gid + half_ * 8;
        size_t g = (((size_t)bb * Hh + hh) * Wd + w0 + m) * Cc;
        #pragma unroll
        for (int jc = 0; jc < 2; jc++) {
            int col = jc * 8 + tg * 2;
            float dx0 = acc2[jc][half_ * 2 + 0];
            float dx1 = acc2[jc][half_ * 2 + 1];
            float2 xr = *(const float2*)(x + g + col);
            float2 bv = *(const float2*)(b2s + col);
            float2 o;
            o.x = fminf(fmaxf(xr.x + dx0 + bv.x, 0.f), 1.f);
            o.y = fminf(fmaxf(xr.y + dx1 + bv.y, 0.f), 1.f);
            *(float2*)(out + g + col) = o;
        }
    }
}

extern "C" void kernel_launch(void* const* d_in, const int* in_sizes, int n_in,
                              void* d_out, int out_size)
{
    const float* x    = (const float*)d_in[0];
    const float* perc = (const float*)d_in[1];
    const float* W1   = (const float*)d_in[2];
    const float* b1   = (const float*)d_in[3];
    const float* W2   = (const float*)d_in[4];
    const float* b2   = (const float*)d_in[5];
    float* out = (float*)d_out;
    (void)in_sizes; (void)n_in; (void)out_size;

    dim3 grid(Wd / MT, Hh, Bb);   // (4, 512, 8)
    nca_mma_kernel<<<grid, NT>>>(x, perc, W1, b1, W2, b2, out);
}

// round 5
// speedup vs baseline: 5.8812x; 1.1061x over previous
#include <cuda_runtime.h>
#include <cuda_fp16.h>
#include <cstdint>

// Neural CA step via mma.sync (fp16 x fp16 -> f32).  R5: perception register
// blocking (2 px/thread), N-split GEMM1 folded into GEMM2 (regs ~115 -> ~84,
// 3 CTAs/SM).
// x[8,512,512,16] -> perception[48] -> [48->128 relu] -> [128->16] -> +x, clip.

#define Bb 8
#define Hh 512
#define Wd 512
#define Cc 16
#define CK 48
#define HID 128
#define MT 128
#define NT 256

#define SP 56          // S row pitch in halves
#define W1P 56
#define W2P 136

__device__ __forceinline__ uint32_t h2u(__half2 h) {
    uint32_t u;
    __builtin_memcpy(&u, &h, 4);
    return u;
}

__device__ __forceinline__ void mma16816(float& c0, float& c1, float& c2, float& c3,
                                         uint32_t a0, uint32_t a1, uint32_t a2, uint32_t a3,
                                         uint32_t b0, uint32_t b1)
{
    asm volatile(
        "mma.sync.aligned.m16n8k16.row.col.f32.f16.f16.f32 "
        "{%0,%1,%2,%3}, {%4,%5,%6,%7}, {%8,%9}, {%0,%1,%2,%3};"
        : "+f"(c0), "+f"(c1), "+f"(c2), "+f"(c3)
        : "r"(a0), "r"(a1), "r"(a2), "r"(a3), "r"(b0), "r"(b1));
}

__global__ __launch_bounds__(NT, 3)
void nca_mma_kernel(const float* __restrict__ x,
                    const float* __restrict__ perc,
                    const float* __restrict__ W1,
                    const float* __restrict__ b1,
                    const float* __restrict__ W2,
                    const float* __restrict__ b2,
                    float* __restrict__ out)
{
    __shared__ __half S  [MT * SP];     // perception output [m][k]   14.0 KB
    __shared__ __half W1t[HID * W1P];   // W1^T [n][k]                14.0 KB
    __shared__ __half W2t[Cc * W2P];    // W2^T [n][k]                 4.3 KB
    __shared__ float  b1s[HID];
    __shared__ float  b2s[Cc];
    __shared__ float  pcs[28];

    const int tid = threadIdx.x;
    const int wid = tid >> 5;
    const int lid = tid & 31;
    const int gid = lid >> 2;
    const int tg  = lid & 3;
    const int w0  = blockIdx.x * MT;
    const int hh  = blockIdx.y;
    const int bb  = blockIdx.z;

    // ---- stage weights ----
    for (int u = tid; u < CK * HID; u += NT) {
        int k = u >> 7, n = u & 127;
        W1t[n * W1P + k] = __float2half_rn(W1[u]);
    }
    for (int u = tid; u < HID * Cc; u += NT) {
        int k = u >> 4, n = u & 15;
        W2t[n * W2P + k] = __float2half_rn(W2[u]);
    }
    if (tid < HID) b1s[tid] = b1[tid];
    if (tid < Cc)  b2s[tid] = b2[tid];
    if (tid < 27)  pcs[tid] = perc[tid];
    __syncthreads();

    // ---- perception, 2 adjacent pixels per thread (shared column loads) ----
    {
        const int mg = tid >> 2;          // 0..63 -> pixels 2mg, 2mg+1
        const int cg = tid & 3;           // channel group (4 ch)
        const int mA = mg * 2;
        float4 ap[2][3];                  // [pixel][kk] accumulators
        #pragma unroll
        for (int p = 0; p < 2; p++)
            #pragma unroll
            for (int kk = 0; kk < 3; kk++)
                ap[p][kk] = make_float4(0.f, 0.f, 0.f, 0.f);

        #pragma unroll
        for (int r = 0; r < 3; r++) {
            int gh = hh + r - 1;
            bool okh = (gh >= 0) && (gh < Hh);
            const float* rowp = x + ((((size_t)bb * Hh + gh) * Wd) << 4) + cg * 4;
            float4 col[4];
            #pragma unroll
            for (int jj = 0; jj < 4; jj++) {
                int gw = w0 + mA - 1 + jj;
                col[jj] = (okh && gw >= 0 && gw < Wd)
                          ? *(const float4*)(rowp + ((size_t)gw << 4))
                          : make_float4(0.f, 0.f, 0.f, 0.f);
            }
            #pragma unroll
            for (int j = 0; j < 3; j++) {
                float p0 = pcs[(r*3+j)*3 + 0];
                float p1 = pcs[(r*3+j)*3 + 1];
                float p2 = pcs[(r*3+j)*3 + 2];
                #pragma unroll
                for (int p = 0; p < 2; p++) {
                    float4 xv = col[j + p];
                    ap[p][0].x += p0*xv.x; ap[p][0].y += p0*xv.y; ap[p][0].z += p0*xv.z; ap[p][0].w += p0*xv.w;
                    ap[p][1].x += p1*xv.x; ap[p][1].y += p1*xv.y; ap[p][1].z += p1*xv.z; ap[p][1].w += p1*xv.w;
                    ap[p][2].x += p2*xv.x; ap[p][2].y += p2*xv.y; ap[p][2].z += p2*xv.z; ap[p][2].w += p2*xv.w;
                }
            }
        }
        #pragma unroll
        for (int p = 0; p < 2; p++) {
            float v[12] = {ap[p][0].x, ap[p][1].x, ap[p][2].x,
                           ap[p][0].y, ap[p][1].y, ap[p][2].y,
                           ap[p][0].z, ap[p][1].z, ap[p][2].z,
                           ap[p][0].w, ap[p][1].w, ap[p][2].w};
            __half2* dst = (__half2*)(S + (mA + p) * SP + cg * 12);
            #pragma unroll
            for (int q = 0; q < 6; q++)
                dst[q] = __floats2half2_rn(v[2*q], v[2*q+1]);
        }
    }
    __syncthreads();

    // ---- GEMM1 (N split in two 64-halves) fused with GEMM2 accumulate ----
    const int m0 = wid * 16;

    uint32_t af[3][4];                    // A fragments, cached across halves
    #pragma unroll
    for (int s = 0; s < 3; s++) {
        const __half* base = S + s * 16 + tg * 2;
        af[s][0] = *(const uint32_t*)(base + (m0 + gid)     * SP);
        af[s][1] = *(const uint32_t*)(base + (m0 + gid + 8) * SP);
        af[s][2] = *(const uint32_t*)(base + (m0 + gid)     * SP + 8);
        af[s][3] = *(const uint32_t*)(base + (m0 + gid + 8) * SP + 8);
    }

    float acc2[2][4];
    acc2[0][0] = acc2[0][1] = acc2[0][2] = acc2[0][3] = 0.f;
    acc2[1][0] = acc2[1][1] = acc2[1][2] = acc2[1][3] = 0.f;

    #pragma unroll
    for (int h = 0; h < 2; h++) {
        // H-half [16 x 64]
        float accH[8][4];
        #pragma unroll
        for (int j = 0; j < 8; j++)
            accH[j][0] = accH[j][1] = accH[j][2] = accH[j][3] = 0.f;

        #pragma unroll
        for (int j = 0; j < 8; j++) {
            const __half* bb1 = W1t + ((h * 8 + j) * 8 + gid) * W1P + tg * 2;
            #pragma unroll
            for (int s = 0; s < 3; s++) {
                uint32_t b0 = *(const uint32_t*)(bb1 + s * 16);
                uint32_t b1r = *(const uint32_t*)(bb1 + s * 16 + 8);
                mma16816(accH[j][0], accH[j][1], accH[j][2], accH[j][3],
                         af[s][0], af[s][1], af[s][2], af[s][3], b0, b1r);
            }
        }

        // +b1, relu, pack C-frags -> A-frags for this half
        uint32_t hA[4][4];
        #pragma unroll
        for (int j = 0; j < 8; j++) {
            float2 bj = *(const float2*)(b1s + (h * 8 + j) * 8 + tg * 2);
            float c0 = fmaxf(accH[j][0] + bj.x, 0.f);
            float c1 = fmaxf(accH[j][1] + bj.y, 0.f);
            float c2 = fmaxf(accH[j][2] + bj.x, 0.f);
            float c3 = fmaxf(accH[j][3] + bj.y, 0.f);
            uint32_t lo = h2u(__floats2half2_rn(c0, c1));
            uint32_t hi = h2u(__floats2half2_rn(c2, c3));
            hA[j >> 1][(j & 1) ? 2 : 0] = lo;
            hA[j >> 1][(j & 1) ? 3 : 1] = hi;
        }

        // GEMM2 partial: k-dims [64h, 64h+64)
        #pragma unroll
        for (int jc = 0; jc < 2; jc++) {
            const __half* bb2 = W2t + (jc * 8 + gid) * W2P + h * 64 + tg * 2;
            #pragma unroll
            for (int s = 0; s < 4; s++) {
                uint32_t b0 = *(const uint32_t*)(bb2 + s * 16);
                uint32_t b1r = *(const uint32_t*)(bb2 + s * 16 + 8);
                mma16816(acc2[jc][0], acc2[jc][1], acc2[jc][2], acc2[jc][3],
                         hA[s][0], hA[s][1], hA[s][2], hA[s][3], b0, b1r);
            }
        }
    }

    // ---- epilogue: out = clip(x + dx + b2, 0, 1) ----
    #pragma unroll
    for (int half_ = 0; half_ < 2; half_++) {
        int m = m0 + gid + half_ * 8;
        size_t g = (((size_t)bb * Hh + hh) * Wd + w0 + m) * Cc;
        #pragma unroll
        for (int jc = 0; jc < 2; jc++) {
            int col = jc * 8 + tg * 2;
            float dx0 = acc2[jc][half_ * 2 + 0];
            float dx1 = acc2[jc][half_ * 2 + 1];
            float2 xr = *(const float2*)(x + g + col);
            float2 bv = *(const float2*)(b2s + col);
            float2 o;
            o.x = fminf(fmaxf(xr.x + dx0 + bv.x, 0.f), 1.f);
            o.y = fminf(fmaxf(xr.y + dx1 + bv.y, 0.f), 1.f);
            *(float2*)(out + g + col) = o;
        }
    }
}

extern "C" void kernel_launch(void* const* d_in, const int* in_sizes, int n_in,
                              void* d_out, int out_size)
{
    const float* x    = (const float*)d_in[0];
    const float* perc = (const float*)d_in[1];
    const float* W1   = (const float*)d_in[2];
    const float* b1   = (const float*)d_in[3];
    const float* W2   = (const float*)d_in[4];
    const float* b2   = (const float*)d_in[5];
    float* out = (float*)d_out;
    (void)in_sizes; (void)n_in; (void)out_size;

    dim3 grid(Wd / MT, Hh, Bb);   // (4, 512, 8)
    nca_mma_kernel<<<grid, NT>>>(x, perc, W1, b1, W2, b2, out);
}

// round 6
// speedup vs baseline: 6.6307x; 1.1274x over previous
#include <cuda_runtime.h>
#include <cuda_fp16.h>
#include <cstdint>

// Neural CA step via mma.sync + ldmatrix (fp16 x fp16 -> f32).
// R6: M=32/warp (W1 stream per pixel halved), K-major weight smem with
// conflict-free staging, ldmatrix.x4(.trans) fragment loads.

#define Bb 8
#define Hh 512
#define Wd 512
#define Cc 16
#define CK 48
#define HID 128
#define MT 128
#define NT 128          // 4 warps, 32 px each

#define SPH  56         // S pitch (halves)
#define W1PH 136        // W1s pitch (halves), K-major [k][n]
#define W2PH 24         // W2s pitch (halves), K-major [k][n]

__device__ __forceinline__ uint32_t h2u(__half2 h) {
    uint32_t u; __builtin_memcpy(&u, &h, 4); return u;
}

__device__ __forceinline__ void mma16816(float* c,
                                         uint32_t a0, uint32_t a1, uint32_t a2, uint32_t a3,
                                         uint32_t b0, uint32_t b1)
{
    asm volatile(
        "mma.sync.aligned.m16n8k16.row.col.f32.f16.f16.f32 "
        "{%0,%1,%2,%3}, {%4,%5,%6,%7}, {%8,%9}, {%0,%1,%2,%3};"
        : "+f"(c[0]), "+f"(c[1]), "+f"(c[2]), "+f"(c[3])
        : "r"(a0), "r"(a1), "r"(a2), "r"(a3), "r"(b0), "r"(b1));
}

__device__ __forceinline__ void ldsm4(uint32_t& r0, uint32_t& r1, uint32_t& r2, uint32_t& r3,
                                      uint32_t addr)
{
    asm volatile("ldmatrix.sync.aligned.m8n8.x4.shared.b16 {%0,%1,%2,%3}, [%4];"
                 : "=r"(r0), "=r"(r1), "=r"(r2), "=r"(r3) : "r"(addr));
}
__device__ __forceinline__ void ldsm4t(uint32_t& r0, uint32_t& r1, uint32_t& r2, uint32_t& r3,
                                       uint32_t addr)
{
    asm volatile("ldmatrix.sync.aligned.m8n8.x4.trans.shared.b16 {%0,%1,%2,%3}, [%4];"
                 : "=r"(r0), "=r"(r1), "=r"(r2), "=r"(r3) : "r"(addr));
}

__global__ __launch_bounds__(NT, 4)
void nca_mma_kernel(const float* __restrict__ x,
                    const float* __restrict__ perc,
                    const float* __restrict__ W1,
                    const float* __restrict__ b1,
                    const float* __restrict__ W2,
                    const float* __restrict__ b2,
                    float* __restrict__ out)
{
    __shared__ __half S  [MT * SPH];     // perception [m][k]      14.0 KB
    __shared__ __half W1s[CK * W1PH];    // W1 K-major [k][n]      12.8 KB
    __shared__ __half W2s[HID * W2PH];   // W2 K-major [k][n]       6.0 KB
    __shared__ float  b1s[HID];
    __shared__ float  b2s[Cc];
    __shared__ float  pcs[28];

    const int tid = threadIdx.x;
    const int wid = tid >> 5;
    const int lid = tid & 31;
    const int gid = lid >> 2;
    const int tg  = lid & 3;
    const int w0  = blockIdx.x * MT;
    const int hh  = blockIdx.y;
    const int bb  = blockIdx.z;

    // ---- stage weights, K-major (coalesced LDG, conflict-free STS) ----
    for (int u = tid; u < CK * HID / 2; u += NT) {       // 3072 half2 items
        int k = u >> 6, np = u & 63;
        float2 f = *(const float2*)(W1 + k * HID + np * 2);
        *(__half2*)(W1s + k * W1PH + np * 2) = __floats2half2_rn(f.x, f.y);
    }
    for (int u = tid; u < HID * Cc / 2; u += NT) {       // 1024 items
        int k = u >> 3, np = u & 7;
        float2 f = *(const float2*)(W2 + k * Cc + np * 2);
        *(__half2*)(W2s + k * W2PH + np * 2) = __floats2half2_rn(f.x, f.y);
    }
    b1s[tid] = b1[tid];                                  // NT == HID
    if (tid < Cc) b2s[tid] = b2[tid];
    if (tid < 27) pcs[tid] = perc[tid];
    __syncthreads();

    // ---- perception: 4 adjacent px per thread, one channel group ----
    {
        const int cg = tid & 3;
        const int mA = (tid >> 2) * 4;                   // 0..124
        const bool intr = (hh > 0) && (hh < Hh - 1) && (w0 > 0) && (w0 + MT < Wd);

        float4 ap[4][3];
        #pragma unroll
        for (int p = 0; p < 4; p++)
            #pragma unroll
            for (int kk = 0; kk < 3; kk++)
                ap[p][kk] = make_float4(0.f, 0.f, 0.f, 0.f);

        #pragma unroll
        for (int r = 0; r < 3; r++) {
            int gh = hh + r - 1;
            const float* rp = x + ((((size_t)bb * Hh + gh) * Wd) << 4) + cg * 4;
            float4 col[6];
            if (intr) {
                #pragma unroll
                for (int jj = 0; jj < 6; jj++)
                    col[jj] = *(const float4*)(rp + ((size_t)(w0 + mA - 1 + jj) << 4));
            } else {
                bool okh = (gh >= 0) && (gh < Hh);
                #pragma unroll
                for (int jj = 0; jj < 6; jj++) {
                    int gw = w0 + mA - 1 + jj;
                    col[jj] = (okh && gw >= 0 && gw < Wd)
                              ? *(const float4*)(rp + ((size_t)gw << 4))
                              : make_float4(0.f, 0.f, 0.f, 0.f);
                }
            }
            #pragma unroll
            for (int j = 0; j < 3; j++) {
                float p0 = pcs[(r*3+j)*3 + 0];
                float p1 = pcs[(r*3+j)*3 + 1];
                float p2 = pcs[(r*3+j)*3 + 2];
                #pragma unroll
                for (int p = 0; p < 4; p++) {
                    float4 xv = col[j + p];
                    ap[p][0].x += p0*xv.x; ap[p][0].y += p0*xv.y; ap[p][0].z += p0*xv.z; ap[p][0].w += p0*xv.w;
                    ap[p][1].x += p1*xv.x; ap[p][1].y += p1*xv.y; ap[p][1].z += p1*xv.z; ap[p][1].w += p1*xv.w;
                    ap[p][2].x += p2*xv.x; ap[p][2].y += p2*xv.y; ap[p][2].z += p2*xv.z; ap[p][2].w += p2*xv.w;
                }
            }
        }
        #pragma unroll
        for (int p = 0; p < 4; p++) {
            uint32_t v[6];
            v[0] = h2u(__floats2half2_rn(ap[p][0].x, ap[p][1].x));
            v[1] = h2u(__floats2half2_rn(ap[p][2].x, ap[p][0].y));
            v[2] = h2u(__floats2half2_rn(ap[p][1].y, ap[p][2].y));
            v[3] = h2u(__floats2half2_rn(ap[p][0].z, ap[p][1].z));
            v[4] = h2u(__floats2half2_rn(ap[p][2].z, ap[p][0].w));
            v[5] = h2u(__floats2half2_rn(ap[p][1].w, ap[p][2].w));
            uint32_t* dst = (uint32_t*)(S + (mA + p) * SPH + cg * 12);
            *(uint2*)(dst + 0) = make_uint2(v[0], v[1]);
            *(uint2*)(dst + 2) = make_uint2(v[2], v[3]);
            *(uint2*)(dst + 4) = make_uint2(v[4], v[5]);
        }
    }
    __syncthreads();

    // ---- A fragments (M=32/warp), cached: ldmatrix.x4 per (mt, s) ----
    const int m0 = wid * 32;
    uint32_t af[2][3][4];
    {
        int row_l = (lid & 7) + ((lid >> 3) & 1) * 8;    // 0..15 within tile
        int colh  = ((lid >> 4) & 1) * 8;                // k-half
        #pragma unroll
        for (int mt = 0; mt < 2; mt++)
            #pragma unroll
            for (int s = 0; s < 3; s++) {
                uint32_t a = (uint32_t)__cvta_generic_to_shared(
                    S + (m0 + mt * 16 + row_l) * SPH + s * 16 + colh);
                ldsm4(af[mt][s][0], af[mt][s][1], af[mt][s][2], af[mt][s][3], a);
            }
    }

    float acc2[2][2][4];
    #pragma unroll
    for (int mt = 0; mt < 2; mt++)
        #pragma unroll
        for (int jc = 0; jc < 2; jc++)
            acc2[mt][jc][0] = acc2[mt][jc][1] = acc2[mt][jc][2] = acc2[mt][jc][3] = 0.f;

    // lane address components for trans B loads
    const int bk_l = (lid & 7) + ((lid >> 4) & 1) * 8;   // k row within 16
    const int bn_l = ((lid >> 3) & 1) * 8;               // n-half

    // ---- 8 subtiles of 16 N: GEMM1 -> relu -> GEMM2 fold ----
    #pragma unroll
    for (int q = 0; q < 8; q++) {
        float accH[2][2][4];
        #pragma unroll
        for (int mt = 0; mt < 2; mt++)
            #pragma unroll
            for (int jj = 0; jj < 2; jj++)
                accH[mt][jj][0] = accH[mt][jj][1] = accH[mt][jj][2] = accH[mt][jj][3] = 0.f;

        #pragma unroll
        for (int s = 0; s < 3; s++) {
            uint32_t r0, r1, r2, r3;   // b0(jj0), b0(jj1), b1(jj0), b1(jj1)
            uint32_t a = (uint32_t)__cvta_generic_to_shared(
                W1s + (s * 16 + bk_l) * W1PH + q * 16 + bn_l);
            ldsm4t(r0, r1, r2, r3, a);
            #pragma unroll
            for (int mt = 0; mt < 2; mt++) {
                mma16816(accH[mt][0], af[mt][s][0], af[mt][s][1], af[mt][s][2], af[mt][s][3], r0, r2);
                mma16816(accH[mt][1], af[mt][s][0], af[mt][s][1], af[mt][s][2], af[mt][s][3], r1, r3);
            }
        }

        // +b1, relu, pack to GEMM2 A-frags (k-step = q)
        uint32_t hA[2][4];
        float2 bj0 = *(const float2*)(b1s + q * 16 + tg * 2);
        float2 bj1 = *(const float2*)(b1s + q * 16 + 8 + tg * 2);
        #pragma unroll
        for (int mt = 0; mt < 2; mt++) {
            float c00 = fmaxf(accH[mt][0][0] + bj0.x, 0.f);
            float c01 = fmaxf(accH[mt][0][1] + bj0.y, 0.f);
            float c02 = fmaxf(accH[mt][0][2] + bj0.x, 0.f);
            float c03 = fmaxf(accH[mt][0][3] + bj0.y, 0.f);
            float c10 = fmaxf(accH[mt][1][0] + bj1.x, 0.f);
            float c11 = fmaxf(accH[mt][1][1] + bj1.y, 0.f);
            float c12 = fmaxf(accH[mt][1][2] + bj1.x, 0.f);
            float c13 = fmaxf(accH[mt][1][3] + bj1.y, 0.f);
            hA[mt][0] = h2u(__floats2half2_rn(c00, c01));  // row g,   k-low
            hA[mt][1] = h2u(__floats2half2_rn(c02, c03));  // row g+8, k-low
            hA[mt][2] = h2u(__floats2half2_rn(c10, c11));  // row g,   k-high
            hA[mt][3] = h2u(__floats2half2_rn(c12, c13));  // row g+8, k-high
        }

        // GEMM2 partial: k-slice [16q, 16q+16)
        {
            uint32_t r0, r1, r2, r3;   // b0(jc0), b0(jc1), b1(jc0), b1(jc1)
            uint32_t a = (uint32_t)__cvta_generic_to_shared(
                W2s + (q * 16 + bk_l) * W2PH + bn_l);
            ldsm4t(r0, r1, r2, r3, a);
            #pragma unroll
            for (int mt = 0; mt < 2; mt++) {
                mma16816(acc2[mt][0], hA[mt][0], hA[mt][1], hA[mt][2], hA[mt][3], r0, r2);
                mma16816(acc2[mt][1], hA[mt][0], hA[mt][1], hA[mt][2], hA[mt][3], r1, r3);
            }
        }
    }

    // ---- epilogue: out = clip(x + dx + b2, 0, 1) ----
    #pragma unroll
    for (int mt = 0; mt < 2; mt++) {
        #pragma unroll
        for (int half_ = 0; half_ < 2; half_++) {
            int m = m0 + mt * 16 + gid + half_ * 8;
            size_t g = (((size_t)bb * Hh + hh) * Wd + w0 + m) * Cc;
            #pragma unroll
            for (int jc = 0; jc < 2; jc++) {
                int col = jc * 8 + tg * 2;
                float dx0 = acc2[mt][jc][half_ * 2 + 0];
                float dx1 = acc2[mt][jc][half_ * 2 + 1];
                float2 xr = *(const float2*)(x + g + col);
                float2 bv = *(const float2*)(b2s + col);
                float2 o;
                o.x = fminf(fmaxf(xr.x + dx0 + bv.x, 0.f), 1.f);
                o.y = fminf(fmaxf(xr.y + dx1 + bv.y, 0.f), 1.f);
                *(float2*)(out + g + col) = o;
            }
        }
    }
}

extern "C" void kernel_launch(void* const* d_in, const int* in_sizes, int n_in,
                              void* d_out, int out_size)
{
    const float* x    = (const float*)d_in[0];
    const float* perc = (const float*)d_in[1];
    const float* W1   = (const float*)d_in[2];
    const float* b1   = (const float*)d_in[3];
    const float* W2   = (const float*)d_in[4];
    const float* b2   = (const float*)d_in[5];
    float* out = (float*)d_out;
    (void)in_sizes; (void)n_in; (void)out_size;

    dim3 grid(Wd / MT, Hh, Bb);   // (4, 512, 8)
    nca_mma_kernel<<<grid, NT>>>(x, perc, W1, b1, W2, b2, out);
}

// round 7
// speedup vs baseline: 7.2965x; 1.1004x over previous
#include <cuda_runtime.h>
#include <cuda_fp16.h>
#include <cstdint>

// Neural CA step via mma.sync + ldmatrix (fp16 x fp16 -> f32).
// R7: sparse perception (identity 1 tap, sobel zero col/row), 2px x 2it per
// thread, launch_bounds(128,5) for occupancy.

#define Bb 8
#define Hh 512
#define Wd 512
#define Cc 16
#define CK 48
#define HID 128
#define MT 128
#define NT 128          // 4 warps, 32 px each

#define SPH  56         // S pitch (halves)
#define W1PH 136        // W1s pitch (halves), K-major [k][n]
#define W2PH 24         // W2s pitch (halves), K-major [k][n]

__device__ __forceinline__ uint32_t h2u(__half2 h) {
    uint32_t u; __builtin_memcpy(&u, &h, 4); return u;
}

__device__ __forceinline__ void mma16816(float* c,
                                         uint32_t a0, uint32_t a1, uint32_t a2, uint32_t a3,
                                         uint32_t b0, uint32_t b1)
{
    asm volatile(
        "mma.sync.aligned.m16n8k16.row.col.f32.f16.f16.f32 "
        "{%0,%1,%2,%3}, {%4,%5,%6,%7}, {%8,%9}, {%0,%1,%2,%3};"
        : "+f"(c[0]), "+f"(c[1]), "+f"(c[2]), "+f"(c[3])
        : "r"(a0), "r"(a1), "r"(a2), "r"(a3), "r"(b0), "r"(b1));
}

__device__ __forceinline__ void ldsm4(uint32_t& r0, uint32_t& r1, uint32_t& r2, uint32_t& r3,
                                      uint32_t addr)
{
    asm volatile("ldmatrix.sync.aligned.m8n8.x4.shared.b16 {%0,%1,%2,%3}, [%4];"
                 : "=r"(r0), "=r"(r1), "=r"(r2), "=r"(r3) : "r"(addr));
}
__device__ __forceinline__ void ldsm4t(uint32_t& r0, uint32_t& r1, uint32_t& r2, uint32_t& r3,
                                       uint32_t addr)
{
    asm volatile("ldmatrix.sync.aligned.m8n8.x4.trans.shared.b16 {%0,%1,%2,%3}, [%4];"
                 : "=r"(r0), "=r"(r1), "=r"(r2), "=r"(r3) : "r"(addr));
}

__device__ __forceinline__ void fma4(float4& a, float p, float4 v) {
    a.x += p * v.x; a.y += p * v.y; a.z += p * v.z; a.w += p * v.w;
}

__global__ __launch_bounds__(NT, 5)
void nca_mma_kernel(const float* __restrict__ x,
                    const float* __restrict__ perc,
                    const float* __restrict__ W1,
                    const float* __restrict__ b1,
                    const float* __restrict__ W2,
                    const float* __restrict__ b2,
                    float* __restrict__ out)
{
    __shared__ __half S  [MT * SPH];     // perception [m][k]      14.0 KB
    __shared__ __half W1s[CK * W1PH];    // W1 K-major [k][n]      12.8 KB
    __shared__ __half W2s[HID * W2PH];   // W2 K-major [k][n]       6.0 KB
    __shared__ float  b1s[HID];
    __shared__ float  b2s[Cc];
    __shared__ float  pcs[28];

    const int tid = threadIdx.x;
    const int wid = tid >> 5;
    const int lid = tid & 31;
    const int gid = lid >> 2;
    const int tg  = lid & 3;
    const int w0  = blockIdx.x * MT;
    const int hh  = blockIdx.y;
    const int bb  = blockIdx.z;

    // ---- stage weights, K-major (coalesced LDG, conflict-free STS) ----
    for (int u = tid; u < CK * HID / 2; u += NT) {
        int k = u >> 6, np = u & 63;
        float2 f = *(const float2*)(W1 + k * HID + np * 2);
        *(__half2*)(W1s + k * W1PH + np * 2) = __floats2half2_rn(f.x, f.y);
    }
    for (int u = tid; u < HID * Cc / 2; u += NT) {
        int k = u >> 3, np = u & 7;
        float2 f = *(const float2*)(W2 + k * Cc + np * 2);
        *(__half2*)(W2s + k * W2PH + np * 2) = __floats2half2_rn(f.x, f.y);
    }
    b1s[tid] = b1[tid];
    if (tid < Cc) b2s[tid] = b2[tid];
    if (tid < 27) pcs[tid] = perc[tid];
    __syncthreads();

    // ---- sparse perception: identity(center), sobel-x (j!=1), sobel-y (r!=1) ----
    {
        const int cg = tid & 3;
        const int mgB = (tid >> 2) * 4;
        #pragma unroll
        for (int it = 0; it < 2; ++it) {
            const int mA = mgB + it * 2;                 // 2 px: mA, mA+1
            float4 id0, id1;
            float4 sx0 = {0,0,0,0}, sx1 = {0,0,0,0};
            float4 sy0 = {0,0,0,0}, sy1 = {0,0,0,0};
            const bool intr = (hh > 0) && (hh < Hh - 1) &&
                              (w0 + mA > 0) && (w0 + mA + 2 < Wd);

            #pragma unroll
            for (int r = 0; r < 3; r++) {
                int gh = hh + r - 1;
                const float* rp = x + ((((size_t)bb * Hh + gh) * Wd) << 4) + cg * 4;
                float4 col[4];
                if (intr) {
                    #pragma unroll
                    for (int jj = 0; jj < 4; jj++)
                        col[jj] = *(const float4*)(rp + ((size_t)(w0 + mA - 1 + jj) << 4));
                } else {
                    bool okh = (gh >= 0) && (gh < Hh);
                    #pragma unroll
                    for (int jj = 0; jj < 4; jj++) {
                        int gw = w0 + mA - 1 + jj;
                        col[jj] = (okh && gw >= 0 && gw < Wd)
                                  ? *(const float4*)(rp + ((size_t)gw << 4))
                                  : make_float4(0.f, 0.f, 0.f, 0.f);
                    }
                }
                // sobel-x: taps at j=0,2 (middle column zero)
                float pA = pcs[(r * 3 + 0) * 3 + 1];
                float pB = pcs[(r * 3 + 2) * 3 + 1];
                fma4(sx0, pA, col[0]); fma4(sx0, pB, col[2]);
                fma4(sx1, pA, col[1]); fma4(sx1, pB, col[3]);
                if (r != 1) {
                    // sobel-y: full row taps (middle row zero)
                    float q0 = pcs[(r * 3 + 0) * 3 + 2];
                    float q1 = pcs[(r * 3 + 1) * 3 + 2];
                    float q2 = pcs[(r * 3 + 2) * 3 + 2];
                    fma4(sy0, q0, col[0]); fma4(sy0, q1, col[1]); fma4(sy0, q2, col[2]);
                    fma4(sy1, q0, col[1]); fma4(sy1, q1, col[2]); fma4(sy1, q2, col[3]);
                } else {
                    // identity: center tap only
                    float pc = pcs[4 * 3 + 0];
                    id0 = make_float4(pc * col[1].x, pc * col[1].y, pc * col[1].z, pc * col[1].w);
                    id1 = make_float4(pc * col[2].x, pc * col[2].y, pc * col[2].z, pc * col[2].w);
                }
            }
            // pack [id,sx,sy] per channel -> 12 halves at S[m][cg*12]
            {
                uint32_t v[6];
                v[0] = h2u(__floats2half2_rn(id0.x, sx0.x));
                v[1] = h2u(__floats2half2_rn(sy0.x, id0.y));
                v[2] = h2u(__floats2half2_rn(sx0.y, sy0.y));
                v[3] = h2u(__floats2half2_rn(id0.z, sx0.z));
                v[4] = h2u(__floats2half2_rn(sy0.z, id0.w));
                v[5] = h2u(__floats2half2_rn(sx0.w, sy0.w));
                uint32_t* dst = (uint32_t*)(S + mA * SPH + cg * 12);
                *(uint2*)(dst + 0) = make_uint2(v[0], v[1]);
                *(uint2*)(dst + 2) = make_uint2(v[2], v[3]);
                *(uint2*)(dst + 4) = make_uint2(v[4], v[5]);
                v[0] = h2u(__floats2half2_rn(id1.x, sx1.x));
                v[1] = h2u(__floats2half2_rn(sy1.x, id1.y));
                v[2] = h2u(__floats2half2_rn(sx1.y, sy1.y));
                v[3] = h2u(__floats2half2_rn(id1.z, sx1.z));
                v[4] = h2u(__floats2half2_rn(sy1.z, id1.w));
                v[5] = h2u(__floats2half2_rn(sx1.w, sy1.w));
                dst = (uint32_t*)(S + (mA + 1) * SPH + cg * 12);
                *(uint2*)(dst + 0) = make_uint2(v[0], v[1]);
                *(uint2*)(dst + 2) = make_uint2(v[2], v[3]);
                *(uint2*)(dst + 4) = make_uint2(v[4], v[5]);
            }
        }
    }
    __syncthreads();

    // ---- A fragments (M=32/warp) ----
    const int m0 = wid * 32;
    uint32_t af[2][3][4];
    {
        int row_l = (lid & 7) + ((lid >> 3) & 1) * 8;
        int colh  = ((lid >> 4) & 1) * 8;
        #pragma unroll
        for (int mt = 0; mt < 2; mt++)
            #pragma unroll
            for (int s = 0; s < 3; s++) {
                uint32_t a = (uint32_t)__cvta_generic_to_shared(
                    S + (m0 + mt * 16 + row_l) * SPH + s * 16 + colh);
                ldsm4(af[mt][s][0], af[mt][s][1], af[mt][s][2], af[mt][s][3], a);
            }
    }

    float acc2[2][2][4];
    #pragma unroll
    for (int mt = 0; mt < 2; mt++)
        #pragma unroll
        for (int jc = 0; jc < 2; jc++)
            acc2[mt][jc][0] = acc2[mt][jc][1] = acc2[mt][jc][2] = acc2[mt][jc][3] = 0.f;

    const int bk_l = (lid & 7) + ((lid >> 4) & 1) * 8;
    const int bn_l = ((lid >> 3) & 1) * 8;

    // ---- 8 subtiles of 16 N: GEMM1 -> relu -> GEMM2 fold ----
    #pragma unroll
    for (int q = 0; q < 8; q++) {
        float accH[2][2][4];
        #pragma unroll
        for (int mt = 0; mt < 2; mt++)
            #pragma unroll
            for (int jj = 0; jj < 2; jj++)
                accH[mt][jj][0] = accH[mt][jj][1] = accH[mt][jj][2] = accH[mt][jj][3] = 0.f;

        #pragma unroll
        for (int s = 0; s < 3; s++) {
            uint32_t r0, r1, r2, r3;
            uint32_t a = (uint32_t)__cvta_generic_to_shared(
                W1s + (s * 16 + bk_l) * W1PH + q * 16 + bn_l);
            ldsm4t(r0, r1, r2, r3, a);
            #pragma unroll
            for (int mt = 0; mt < 2; mt++) {
                mma16816(accH[mt][0], af[mt][s][0], af[mt][s][1], af[mt][s][2], af[mt][s][3], r0, r2);
                mma16816(accH[mt][1], af[mt][s][0], af[mt][s][1], af[mt][s][2], af[mt][s][3], r1, r3);
            }
        }

        uint32_t hA[2][4];
        float2 bj0 = *(const float2*)(b1s + q * 16 + tg * 2);
        float2 bj1 = *(const float2*)(b1s + q * 16 + 8 + tg * 2);
        #pragma unroll
        for (int mt = 0; mt < 2; mt++) {
            float c00 = fmaxf(accH[mt][0][0] + bj0.x, 0.f);
            float c01 = fmaxf(accH[mt][0][1] + bj0.y, 0.f);
            float c02 = fmaxf(accH[mt][0][2] + bj0.x, 0.f);
            float c03 = fmaxf(accH[mt][0][3] + bj0.y, 0.f);
            float c10 = fmaxf(accH[mt][1][0] + bj1.x, 0.f);
            float c11 = fmaxf(accH[mt][1][1] + bj1.y, 0.f);
            float c12 = fmaxf(accH[mt][1][2] + bj1.x, 0.f);
            float c13 = fmaxf(accH[mt][1][3] + bj1.y, 0.f);
            hA[mt][0] = h2u(__floats2half2_rn(c00, c01));
            hA[mt][1] = h2u(__floats2half2_rn(c02, c03));
            hA[mt][2] = h2u(__floats2half2_rn(c10, c11));
            hA[mt][3] = h2u(__floats2half2_rn(c12, c13));
        }

        {
            uint32_t r0, r1, r2, r3;
            uint32_t a = (uint32_t)__cvta_generic_to_shared(
                W2s + (q * 16 + bk_l) * W2PH + bn_l);
            ldsm4t(r0, r1, r2, r3, a);
            #pragma unroll
            for (int mt = 0; mt < 2; mt++) {
                mma16816(acc2[mt][0], hA[mt][0], hA[mt][1], hA[mt][2], hA[mt][3], r0, r2);
                mma16816(acc2[mt][1], hA[mt][0], hA[mt][1], hA[mt][2], hA[mt][3], r1, r3);
            }
        }
    }

    // ---- epilogue: out = clip(x + dx + b2, 0, 1) ----
    #pragma unroll
    for (int mt = 0; mt < 2; mt++) {
        #pragma unroll
        for (int half_ = 0; half_ < 2; half_++) {
            int m = m0 + mt * 16 + gid + half_ * 8;
            size_t g = (((size_t)bb * Hh + hh) * Wd + w0 + m) * Cc;
            #pragma unroll
            for (int jc = 0; jc < 2; jc++) {
                int col = jc * 8 + tg * 2;
                float dx0 = acc2[mt][jc][half_ * 2 + 0];
                float dx1 = acc2[mt][jc][half_ * 2 + 1];
                float2 xr = *(const float2*)(x + g + col);
                float2 bv = *(const float2*)(b2s + col);
                float2 o;
                o.x = fminf(fmaxf(xr.x + dx0 + bv.x, 0.f), 1.f);
                o.y = fminf(fmaxf(xr.y + dx1 + bv.y, 0.f), 1.f);
                *(float2*)(out + g + col) = o;
            }
        }
    }
}

extern "C" void kernel_launch(void* const* d_in, const int* in_sizes, int n_in,
                              void* d_out, int out_size)
{
    const float* x    = (const float*)d_in[0];
    const float* perc = (const float*)d_in[1];
    const float* W1   = (const float*)d_in[2];
    const float* b1   = (const float*)d_in[3];
    const float* W2   = (const float*)d_in[4];
    const float* b2   = (const float*)d_in[5];
    float* out = (float*)d_out;
    (void)in_sizes; (void)n_in; (void)out_size;

    dim3 grid(Wd / MT, Hh, Bb);   // (4, 512, 8)
    nca_mma_kernel<<<grid, NT>>>(x, perc, W1, b1, W2, b2, out);
}

// round 8
// speedup vs baseline: 9.5197x; 1.3047x over previous
#include <cuda_runtime.h>
#include <cuda_fp16.h>
#include <cstdint>

// Neural CA step via mma.sync + ldmatrix (fp16 x fp16 -> f32).
// R8: 4-row persistent CTA (weights staged once per 512 px, grid /4),
// launch_bounds(128,6) for 6 CTAs/SM.

#define Bb 8
#define Hh 512
#define Wd 512
#define Cc 16
#define CK 48
#define HID 128
#define MT 128
#define NT 128          // 4 warps, 32 px each
#define ROWS 4          // rows per CTA

#define SPH  56         // S pitch (halves)
#define W1PH 136        // W1s pitch (halves), K-major [k][n]
#define W2PH 24         // W2s pitch (halves), K-major [k][n]

__device__ __forceinline__ uint32_t h2u(__half2 h) {
    uint32_t u; __builtin_memcpy(&u, &h, 4); return u;
}

__device__ __forceinline__ void mma16816(float* c,
                                         uint32_t a0, uint32_t a1, uint32_t a2, uint32_t a3,
                                         uint32_t b0, uint32_t b1)
{
    asm volatile(
        "mma.sync.aligned.m16n8k16.row.col.f32.f16.f16.f32 "
        "{%0,%1,%2,%3}, {%4,%5,%6,%7}, {%8,%9}, {%0,%1,%2,%3};"
        : "+f"(c[0]), "+f"(c[1]), "+f"(c[2]), "+f"(c[3])
        : "r"(a0), "r"(a1), "r"(a2), "r"(a3), "r"(b0), "r"(b1));
}

__device__ __forceinline__ void ldsm4(uint32_t& r0, uint32_t& r1, uint32_t& r2, uint32_t& r3,
                                      uint32_t addr)
{
    asm volatile("ldmatrix.sync.aligned.m8n8.x4.shared.b16 {%0,%1,%2,%3}, [%4];"
                 : "=r"(r0), "=r"(r1), "=r"(r2), "=r"(r3) : "r"(addr));
}
__device__ __forceinline__ void ldsm4t(uint32_t& r0, uint32_t& r1, uint32_t& r2, uint32_t& r3,
                                       uint32_t addr)
{
    asm volatile("ldmatrix.sync.aligned.m8n8.x4.trans.shared.b16 {%0,%1,%2,%3}, [%4];"
                 : "=r"(r0), "=r"(r1), "=r"(r2), "=r"(r3) : "r"(addr));
}

__device__ __forceinline__ void fma4(float4& a, float p, float4 v) {
    a.x += p * v.x; a.y += p * v.y; a.z += p * v.z; a.w += p * v.w;
}

__global__ __launch_bounds__(NT, 6)
void nca_mma_kernel(const float* __restrict__ x,
                    const float* __restrict__ perc,
                    const float* __restrict__ W1,
                    const float* __restrict__ b1,
                    const float* __restrict__ W2,
                    const float* __restrict__ b2,
                    float* __restrict__ out)
{
    __shared__ __half S  [MT * SPH];     // perception [m][k]      14.0 KB
    __shared__ __half W1s[CK * W1PH];    // W1 K-major [k][n]      12.8 KB
    __shared__ __half W2s[HID * W2PH];   // W2 K-major [k][n]       6.0 KB
    __shared__ float  b1s[HID];
    __shared__ float  b2s[Cc];
    __shared__ float  pcs[28];

    const int tid = threadIdx.x;
    const int wid = tid >> 5;
    const int lid = tid & 31;
    const int gid = lid >> 2;
    const int tg  = lid & 3;
    const int w0  = blockIdx.x * MT;
    const int h0  = blockIdx.y * ROWS;
    const int bb  = blockIdx.z;

    // ---- stage weights once per CTA (K-major, conflict-free STS) ----
    for (int u = tid; u < CK * HID / 2; u += NT) {
        int k = u >> 6, np = u & 63;
        float2 f = *(const float2*)(W1 + k * HID + np * 2);
        *(__half2*)(W1s + k * W1PH + np * 2) = __floats2half2_rn(f.x, f.y);
    }
    for (int u = tid; u < HID * Cc / 2; u += NT) {
        int k = u >> 3, np = u & 7;
        float2 f = *(const float2*)(W2 + k * Cc + np * 2);
        *(__half2*)(W2s + k * W2PH + np * 2) = __floats2half2_rn(f.x, f.y);
    }
    b1s[tid] = b1[tid];
    if (tid < Cc) b2s[tid] = b2[tid];
    if (tid < 27) pcs[tid] = perc[tid];
    __syncthreads();

    // lane address components (row-invariant)
    const int cg  = tid & 3;
    const int mgB = (tid >> 2) * 4;
    const int m0  = wid * 32;
    const int row_l = (lid & 7) + ((lid >> 3) & 1) * 8;
    const int colh  = ((lid >> 4) & 1) * 8;
    const int bk_l = (lid & 7) + ((lid >> 4) & 1) * 8;
    const int bn_l = ((lid >> 3) & 1) * 8;

    #pragma unroll 1
    for (int ri = 0; ri < ROWS; ri++) {
        const int hh = h0 + ri;
        if (ri) __syncthreads();   // S of previous iter fully consumed

        // ---- sparse perception: identity(center), sobel-x(j!=1), sobel-y(r!=1) ----
        #pragma unroll
        for (int it = 0; it < 2; ++it) {
            const int mA = mgB + it * 2;
            float4 id0, id1;
            float4 sx0 = {0,0,0,0}, sx1 = {0,0,0,0};
            float4 sy0 = {0,0,0,0}, sy1 = {0,0,0,0};
            const bool intr = (hh > 0) && (hh < Hh - 1) &&
                              (w0 + mA > 0) && (w0 + mA + 2 < Wd);

            #pragma unroll
            for (int r = 0; r < 3; r++) {
                int gh = hh + r - 1;
                const float* rp = x + ((((size_t)bb * Hh + gh) * Wd) << 4) + cg * 4;
                float4 col[4];
                if (intr) {
                    #pragma unroll
                    for (int jj = 0; jj < 4; jj++)
                        col[jj] = *(const float4*)(rp + ((size_t)(w0 + mA - 1 + jj) << 4));
                } else {
                    bool okh = (gh >= 0) && (gh < Hh);
                    #pragma unroll
                    for (int jj = 0; jj < 4; jj++) {
                        int gw = w0 + mA - 1 + jj;
                        col[jj] = (okh && gw >= 0 && gw < Wd)
                                  ? *(const float4*)(rp + ((size_t)gw << 4))
                                  : make_float4(0.f, 0.f, 0.f, 0.f);
                    }
                }
                float pA = pcs[(r * 3 + 0) * 3 + 1];
                float pB = pcs[(r * 3 + 2) * 3 + 1];
                fma4(sx0, pA, col[0]); fma4(sx0, pB, col[2]);
                fma4(sx1, pA, col[1]); fma4(sx1, pB, col[3]);
                if (r != 1) {
                    float q0 = pcs[(r * 3 + 0) * 3 + 2];
                    float q1 = pcs[(r * 3 + 1) * 3 + 2];
                    float q2 = pcs[(r * 3 + 2) * 3 + 2];
                    fma4(sy0, q0, col[0]); fma4(sy0, q1, col[1]); fma4(sy0, q2, col[2]);
                    fma4(sy1, q0, col[1]); fma4(sy1, q1, col[2]); fma4(sy1, q2, col[3]);
                } else {
                    float pc = pcs[4 * 3 + 0];
                    id0 = make_float4(pc * col[1].x, pc * col[1].y, pc * col[1].z, pc * col[1].w);
                    id1 = make_float4(pc * col[2].x, pc * col[2].y, pc * col[2].z, pc * col[2].w);
                }
            }
            uint32_t v[6];
            v[0] = h2u(__floats2half2_rn(id0.x, sx0.x));
            v[1] = h2u(__floats2half2_rn(sy0.x, id0.y));
            v[2] = h2u(__floats2half2_rn(sx0.y, sy0.y));
            v[3] = h2u(__floats2half2_rn(id0.z, sx0.z));
            v[4] = h2u(__floats2half2_rn(sy0.z, id0.w));
            v[5] = h2u(__floats2half2_rn(sx0.w, sy0.w));
            uint32_t* dst = (uint32_t*)(S + mA * SPH + cg * 12);
            *(uint2*)(dst + 0) = make_uint2(v[0], v[1]);
            *(uint2*)(dst + 2) = make_uint2(v[2], v[3]);
            *(uint2*)(dst + 4) = make_uint2(v[4], v[5]);
            v[0] = h2u(__floats2half2_rn(id1.x, sx1.x));
            v[1] = h2u(__floats2half2_rn(sy1.x, id1.y));
            v[2] = h2u(__floats2half2_rn(sx1.y, sy1.y));
            v[3] = h2u(__floats2half2_rn(id1.z, sx1.z));
            v[4] = h2u(__floats2half2_rn(sy1.z, id1.w));
            v[5] = h2u(__floats2half2_rn(sx1.w, sy1.w));
            dst = (uint32_t*)(S + (mA + 1) * SPH + cg * 12);
            *(uint2*)(dst + 0) = make_uint2(v[0], v[1]);
            *(uint2*)(dst + 2) = make_uint2(v[2], v[3]);
            *(uint2*)(dst + 4) = make_uint2(v[4], v[5]);
        }
        __syncthreads();

        // ---- A fragments (M=32/warp) ----
        uint32_t af[2][3][4];
        #pragma unroll
        for (int mt = 0; mt < 2; mt++)
            #pragma unroll
            for (int s = 0; s < 3; s++) {
                uint32_t a = (uint32_t)__cvta_generic_to_shared(
                    S + (m0 + mt * 16 + row_l) * SPH + s * 16 + colh);
                ldsm4(af[mt][s][0], af[mt][s][1], af[mt][s][2], af[mt][s][3], a);
            }

        float acc2[2][2][4];
        #pragma unroll
        for (int mt = 0; mt < 2; mt++)
            #pragma unroll
            for (int jc = 0; jc < 2; jc++)
                acc2[mt][jc][0] = acc2[mt][jc][1] = acc2[mt][jc][2] = acc2[mt][jc][3] = 0.f;

        // ---- 8 subtiles of 16 N: GEMM1 -> relu -> GEMM2 fold ----
        #pragma unroll
        for (int q = 0; q < 8; q++) {
            float accH[2][2][4];
            #pragma unroll
            for (int mt = 0; mt < 2; mt++)
                #pragma unroll
                for (int jj = 0; jj < 2; jj++)
                    accH[mt][jj][0] = accH[mt][jj][1] = accH[mt][jj][2] = accH[mt][jj][3] = 0.f;

            #pragma unroll
            for (int s = 0; s < 3; s++) {
                uint32_t r0, r1, r2, r3;
                uint32_t a = (uint32_t)__cvta_generic_to_shared(
                    W1s + (s * 16 + bk_l) * W1PH + q * 16 + bn_l);
                ldsm4t(r0, r1, r2, r3, a);
                #pragma unroll
                for (int mt = 0; mt < 2; mt++) {
                    mma16816(accH[mt][0], af[mt][s][0], af[mt][s][1], af[mt][s][2], af[mt][s][3], r0, r2);
                    mma16816(accH[mt][1], af[mt][s][0], af[mt][s][1], af[mt][s][2], af[mt][s][3], r1, r3);
                }
            }

            uint32_t hA[2][4];
            float2 bj0 = *(const float2*)(b1s + q * 16 + tg * 2);
            float2 bj1 = *(const float2*)(b1s + q * 16 + 8 + tg * 2);
            #pragma unroll
            for (int mt = 0; mt < 2; mt++) {
                float c00 = fmaxf(accH[mt][0][0] + bj0.x, 0.f);
                float c01 = fmaxf(accH[mt][0][1] + bj0.y, 0.f);
                float c02 = fmaxf(accH[mt][0][2] + bj0.x, 0.f);
                float c03 = fmaxf(accH[mt][0][3] + bj0.y, 0.f);
                float c10 = fmaxf(accH[mt][1][0] + bj1.x, 0.f);
                float c11 = fmaxf(accH[mt][1][1] + bj1.y, 0.f);
                float c12 = fmaxf(accH[mt][1][2] + bj1.x, 0.f);
                float c13 = fmaxf(accH[mt][1][3] + bj1.y, 0.f);
                hA[mt][0] = h2u(__floats2half2_rn(c00, c01));
                hA[mt][1] = h2u(__floats2half2_rn(c02, c03));
                hA[mt][2] = h2u(__floats2half2_rn(c10, c11));
                hA[mt][3] = h2u(__floats2half2_rn(c12, c13));
            }

            {
                uint32_t r0, r1, r2, r3;
                uint32_t a = (uint32_t)__cvta_generic_to_shared(
                    W2s + (q * 16 + bk_l) * W2PH + bn_l);
                ldsm4t(r0, r1, r2, r3, a);
                #pragma unroll
                for (int mt = 0; mt < 2; mt++) {
                    mma16816(acc2[mt][0], hA[mt][0], hA[mt][1], hA[mt][2], hA[mt][3], r0, r2);
                    mma16816(acc2[mt][1], hA[mt][0], hA[mt][1], hA[mt][2], hA[mt][3], r1, r3);
                }
            }
        }

        // ---- epilogue: out = clip(x + dx + b2, 0, 1) ----
        #pragma unroll
        for (int mt = 0; mt < 2; mt++) {
            #pragma unroll
            for (int half_ = 0; half_ < 2; half_++) {
                int m = m0 + mt * 16 + gid + half_ * 8;
                size_t g = (((size_t)bb * Hh + hh) * Wd + w0 + m) * Cc;
                #pragma unroll
                for (int jc = 0; jc < 2; jc++) {
                    int col = jc * 8 + tg * 2;
                    float dx0 = acc2[mt][jc][half_ * 2 + 0];
                    float dx1 = acc2[mt][jc][half_ * 2 + 1];
                    float2 xr = *(const float2*)(x + g + col);
                    float2 bv = *(const float2*)(b2s + col);
                    float2 o;
                    o.x = fminf(fmaxf(xr.x + dx0 + bv.x, 0.f), 1.f);
                    o.y = fminf(fmaxf(xr.y + dx1 + bv.y, 0.f), 1.f);
                    *(float2*)(out + g + col) = o;
                }
            }
        }
    }
}

extern "C" void kernel_launch(void* const* d_in, const int* in_sizes, int n_in,
                              void* d_out, int out_size)
{
    const float* x    = (const float*)d_in[0];
    const float* perc = (const float*)d_in[1];
    const float* W1   = (const float*)d_in[2];
    const float* b1   = (const float*)d_in[3];
    const float* W2   = (const float*)d_in[4];
    const float* b2   = (const float*)d_in[5];
    float* out = (float*)d_out;
    (void)in_sizes; (void)n_in; (void)out_size;

    dim3 grid(Wd / MT, Hh / ROWS, Bb);   // (4, 128, 8)
    nca_mma_kernel<<<grid, NT>>>(x, perc, W1, b1, W2, b2, out);
}

// round 10
// speedup vs baseline: 9.6512x; 1.0138x over previous
#include <cuda_runtime.h>
#include <cuda_fp16.h>
#include <cstdint>

// Neural CA step via mma.sync + ldmatrix (fp16 x fp16 -> f32).
// R10: revert W1PH to 136 (R9's 72 overlapped rows -> corruption); keep
// half2 bias+relu pack and half2-staged b1 from R9.

#define Bb 8
#define Hh 512
#define Wd 512
#define Cc 16
#define CK 48
#define HID 128
#define MT 128
#define NT 128          // 4 warps, 32 px each
#define ROWS 4          // rows per CTA

#define SPH  56         // S pitch (halves)
#define W1PH 136        // W1s pitch (halves): 128 data + 8 pad, conflict-free
#define W2PH 24         // W2s pitch (halves): 16 data + 8 pad

__device__ __forceinline__ uint32_t h2u(__half2 h) {
    uint32_t u; __builtin_memcpy(&u, &h, 4); return u;
}

__device__ __forceinline__ void mma16816(float* c,
                                         uint32_t a0, uint32_t a1, uint32_t a2, uint32_t a3,
                                         uint32_t b0, uint32_t b1)
{
    asm volatile(
        "mma.sync.aligned.m16n8k16.row.col.f32.f16.f16.f32 "
        "{%0,%1,%2,%3}, {%4,%5,%6,%7}, {%8,%9}, {%0,%1,%2,%3};"
        : "+f"(c[0]), "+f"(c[1]), "+f"(c[2]), "+f"(c[3])
        : "r"(a0), "r"(a1), "r"(a2), "r"(a3), "r"(b0), "r"(b1));
}

__device__ __forceinline__ void ldsm4(uint32_t& r0, uint32_t& r1, uint32_t& r2, uint32_t& r3,
                                      uint32_t addr)
{
    asm volatile("ldmatrix.sync.aligned.m8n8.x4.shared.b16 {%0,%1,%2,%3}, [%4];"
                 : "=r"(r0), "=r"(r1), "=r"(r2), "=r"(r3) : "r"(addr));
}
__device__ __forceinline__ void ldsm4t(uint32_t& r0, uint32_t& r1, uint32_t& r2, uint32_t& r3,
                                       uint32_t addr)
{
    asm volatile("ldmatrix.sync.aligned.m8n8.x4.trans.shared.b16 {%0,%1,%2,%3}, [%4];"
                 : "=r"(r0), "=r"(r1), "=r"(r2), "=r"(r3) : "r"(addr));
}

__device__ __forceinline__ void fma4(float4& a, float p, float4 v) {
    a.x += p * v.x; a.y += p * v.y; a.z += p * v.z; a.w += p * v.w;
}

__global__ __launch_bounds__(NT, 6)
void nca_mma_kernel(const float* __restrict__ x,
                    const float* __restrict__ perc,
                    const float* __restrict__ W1,
                    const float* __restrict__ b1,
                    const float* __restrict__ W2,
                    const float* __restrict__ b2,
                    float* __restrict__ out)
{
    __shared__ __half   S  [MT * SPH];     // perception [m][k]     14.0 KB
    __shared__ __half   W1s[CK * W1PH];    // W1 K-major [k][n]     12.8 KB
    __shared__ __half   W2s[HID * W2PH];   // W2 K-major [k][n]      6.0 KB
    __shared__ __half2  b1h[HID / 2];      // b1 as half2 pairs
    __shared__ float    b2s[Cc];
    __shared__ float    pcs[28];

    const int tid = threadIdx.x;
    const int wid = tid >> 5;
    const int lid = tid & 31;
    const int gid = lid >> 2;
    const int tg  = lid & 3;
    const int w0  = blockIdx.x * MT;
    const int h0  = blockIdx.y * ROWS;
    const int bb  = blockIdx.z;

    // ---- stage weights once per CTA (K-major, conflict-free STS) ----
    for (int u = tid; u < CK * HID / 2; u += NT) {
        int k = u >> 6, np = u & 63;
        float2 f = *(const float2*)(W1 + k * HID + np * 2);
        *(__half2*)(W1s + k * W1PH + np * 2) = __floats2half2_rn(f.x, f.y);
    }
    for (int u = tid; u < HID * Cc / 2; u += NT) {
        int k = u >> 3, np = u & 7;
        float2 f = *(const float2*)(W2 + k * Cc + np * 2);
        *(__half2*)(W2s + k * W2PH + np * 2) = __floats2half2_rn(f.x, f.y);
    }
    if (tid < HID / 2) {
        float2 f = *(const float2*)(b1 + tid * 2);
        b1h[tid] = __floats2half2_rn(f.x, f.y);
    }
    if (tid < Cc) b2s[tid] = b2[tid];
    if (tid < 27) pcs[tid] = perc[tid];
    __syncthreads();

    // lane address components (row-invariant)
    const int cg  = tid & 3;
    const int mgB = (tid >> 2) * 4;
    const int m0  = wid * 32;
    const int row_l = (lid & 7) + ((lid >> 3) & 1) * 8;
    const int colh  = ((lid >> 4) & 1) * 8;
    const int bk_l = (lid & 7) + ((lid >> 4) & 1) * 8;
    const int bn_l = ((lid >> 3) & 1) * 8;
    const __half2 hzero = __floats2half2_rn(0.f, 0.f);

    #pragma unroll 1
    for (int ri = 0; ri < ROWS; ri++) {
        const int hh = h0 + ri;
        if (ri) __syncthreads();   // S of previous iter fully consumed

        // ---- sparse perception: identity(center), sobel-x(j!=1), sobel-y(r!=1) ----
        #pragma unroll
        for (int it = 0; it < 2; ++it) {
            const int mA = mgB + it * 2;
            float4 id0, id1;
            float4 sx0 = {0,0,0,0}, sx1 = {0,0,0,0};
            float4 sy0 = {0,0,0,0}, sy1 = {0,0,0,0};
            const bool intr = (hh > 0) && (hh < Hh - 1) &&
                              (w0 + mA > 0) && (w0 + mA + 2 < Wd);

            #pragma unroll
            for (int r = 0; r < 3; r++) {
                int gh = hh + r - 1;
                const float* rp = x + ((((size_t)bb * Hh + gh) * Wd) << 4) + cg * 4;
                float4 col[4];
                if (intr) {
                    #pragma unroll
                    for (int jj = 0; jj < 4; jj++)
                        col[jj] = *(const float4*)(rp + ((size_t)(w0 + mA - 1 + jj) << 4));
                } else {
                    bool okh = (gh >= 0) && (gh < Hh);
                    #pragma unroll
                    for (int jj = 0; jj < 4; jj++) {
                        int gw = w0 + mA - 1 + jj;
                        col[jj] = (okh && gw >= 0 && gw < Wd)
                                  ? *(const float4*)(rp + ((size_t)gw << 4))
                                  : make_float4(0.f, 0.f, 0.f, 0.f);
                    }
                }
                float pA = pcs[(r * 3 + 0) * 3 + 1];
                float pB = pcs[(r * 3 + 2) * 3 + 1];
                fma4(sx0, pA, col[0]); fma4(sx0, pB, col[2]);
                fma4(sx1, pA, col[1]); fma4(sx1, pB, col[3]);
                if (r != 1) {
                    float q0 = pcs[(r * 3 + 0) * 3 + 2];
                    float q1 = pcs[(r * 3 + 1) * 3 + 2];
                    float q2 = pcs[(r * 3 + 2) * 3 + 2];
                    fma4(sy0, q0, col[0]); fma4(sy0, q1, col[1]); fma4(sy0, q2, col[2]);
                    fma4(sy1, q0, col[1]); fma4(sy1, q1, col[2]); fma4(sy1, q2, col[3]);
                } else {
                    float pc = pcs[4 * 3 + 0];
                    id0 = make_float4(pc * col[1].x, pc * col[1].y, pc * col[1].z, pc * col[1].w);
                    id1 = make_float4(pc * col[2].x, pc * col[2].y, pc * col[2].z, pc * col[2].w);
                }
            }
            uint32_t v[6];
            v[0] = h2u(__floats2half2_rn(id0.x, sx0.x));
            v[1] = h2u(__floats2half2_rn(sy0.x, id0.y));
            v[2] = h2u(__floats2half2_rn(sx0.y, sy0.y));
            v[3] = h2u(__floats2half2_rn(id0.z, sx0.z));
            v[4] = h2u(__floats2half2_rn(sy0.z, id0.w));
            v[5] = h2u(__floats2half2_rn(sx0.w, sy0.w));
            uint32_t* dst = (uint32_t*)(S + mA * SPH + cg * 12);
            *(uint2*)(dst + 0) = make_uint2(v[0], v[1]);
            *(uint2*)(dst + 2) = make_uint2(v[2], v[3]);
            *(uint2*)(dst + 4) = make_uint2(v[4], v[5]);
            v[0] = h2u(__floats2half2_rn(id1.x, sx1.x));
            v[1] = h2u(__floats2half2_rn(sy1.x, id1.y));
            v[2] = h2u(__floats2half2_rn(sx1.y, sy1.y));
            v[3] = h2u(__floats2half2_rn(id1.z, sx1.z));
            v[4] = h2u(__floats2half2_rn(sy1.z, id1.w));
            v[5] = h2u(__floats2half2_rn(sx1.w, sy1.w));
            dst = (uint32_t*)(S + (mA + 1) * SPH + cg * 12);
            *(uint2*)(dst + 0) = make_uint2(v[0], v[1]);
            *(uint2*)(dst + 2) = make_uint2(v[2], v[3]);
            *(uint2*)(dst + 4) = make_uint2(v[4], v[5]);
        }
        __syncthreads();

        // ---- A fragments (M=32/warp) ----
        uint32_t af[2][3][4];
        #pragma unroll
        for (int mt = 0; mt < 2; mt++)
            #pragma unroll
            for (int s = 0; s < 3; s++) {
                uint32_t a = (uint32_t)__cvta_generic_to_shared(
                    S + (m0 + mt * 16 + row_l) * SPH + s * 16 + colh);
                ldsm4(af[mt][s][0], af[mt][s][1], af[mt][s][2], af[mt][s][3], a);
            }

        float acc2[2][2][4];
        #pragma unroll
        for (int mt = 0; mt < 2; mt++)
            #pragma unroll
            for (int jc = 0; jc < 2; jc++)
                acc2[mt][jc][0] = acc2[mt][jc][1] = acc2[mt][jc][2] = acc2[mt][jc][3] = 0.f;

        // ---- 8 subtiles of 16 N: GEMM1 -> half2 bias+relu -> GEMM2 fold ----
        #pragma unroll
        for (int q = 0; q < 8; q++) {
            float accH[2][2][4];
            #pragma unroll
            for (int mt = 0; mt < 2; mt++)
                #pragma unroll
                for (int jj = 0; jj < 2; jj++)
                    accH[mt][jj][0] = accH[mt][jj][1] = accH[mt][jj][2] = accH[mt][jj][3] = 0.f;

            #pragma unroll
            for (int s = 0; s < 3; s++) {
                uint32_t r0, r1, r2, r3;
                uint32_t a = (uint32_t)__cvta_generic_to_shared(
                    W1s + (s * 16 + bk_l) * W1PH + q * 16 + bn_l);
                ldsm4t(r0, r1, r2, r3, a);
                #pragma unroll
                for (int mt = 0; mt < 2; mt++) {
                    mma16816(accH[mt][0], af[mt][s][0], af[mt][s][1], af[mt][s][2], af[mt][s][3], r0, r2);
                    mma16816(accH[mt][1], af[mt][s][0], af[mt][s][1], af[mt][s][2], af[mt][s][3], r1, r3);
                }
            }

            // cvt -> half2, then bias add + relu in half2
            uint32_t hA[2][4];
            __half2 bq0 = b1h[q * 8 + tg];
            __half2 bq1 = b1h[q * 8 + 4 + tg];
            #pragma unroll
            for (int mt = 0; mt < 2; mt++) {
                __half2 p0 = __floats2half2_rn(accH[mt][0][0], accH[mt][0][1]);
                __half2 p1 = __floats2half2_rn(accH[mt][0][2], accH[mt][0][3]);
                __half2 p2 = __floats2half2_rn(accH[mt][1][0], accH[mt][1][1]);
                __half2 p3 = __floats2half2_rn(accH[mt][1][2], accH[mt][1][3]);
                hA[mt][0] = h2u(__hmax2(__hadd2(p0, bq0), hzero));
                hA[mt][1] = h2u(__hmax2(__hadd2(p1, bq0), hzero));
                hA[mt][2] = h2u(__hmax2(__hadd2(p2, bq1), hzero));
                hA[mt][3] = h2u(__hmax2(__hadd2(p3, bq1), hzero));
            }

            {
                uint32_t r0, r1, r2, r3;
                uint32_t a = (uint32_t)__cvta_generic_to_shared(
                    W2s + (q * 16 + bk_l) * W2PH + bn_l);
                ldsm4t(r0, r1, r2, r3, a);
                #pragma unroll
                for (int mt = 0; mt < 2; mt++) {
                    mma16816(acc2[mt][0], hA[mt][0], hA[mt][1], hA[mt][2], hA[mt][3], r0, r2);
                    mma16816(acc2[mt][1], hA[mt][0], hA[mt][1], hA[mt][2], hA[mt][3], r1, r3);
                }
            }
        }

        // ---- epilogue: out = clip(x + dx + b2, 0, 1) ----
        #pragma unroll
        for (int mt = 0; mt < 2; mt++) {
            #pragma unroll
            for (int half_ = 0; half_ < 2; half_++) {
                int m = m0 + mt * 16 + gid + half_ * 8;
                size_t g = (((size_t)bb * Hh + hh) * Wd + w0 + m) * Cc;
                #pragma unroll
                for (int jc = 0; jc < 2; jc++) {
                    int col = jc * 8 + tg * 2;
                    float dx0 = acc2[mt][jc][half_ * 2 + 0];
                    float dx1 = acc2[mt][jc][half_ * 2 + 1];
                    float2 xr = *(const float2*)(x + g + col);
                    float2 bv = *(const float2*)(b2s + col);
                    float2 o;
                    o.x = fminf(fmaxf(xr.x + dx0 + bv.x, 0.f), 1.f);
                    o.y = fminf(fmaxf(xr.y + dx1 + bv.y, 0.f), 1.f);
                    *(float2*)(out + g + col) = o;
                }
            }
        }
    }
}

extern "C" void kernel_launch(void* const* d_in, const int* in_sizes, int n_in,
                              void* d_out, int out_size)
{
    const float* x    = (const float*)d_in[0];
    const float* perc = (const float*)d_in[1];
    const float* W1   = (const float*)d_in[2];
    const float* b1   = (const float*)d_in[3];
    const float* W2   = (const float*)d_in[4];
    const float* b2   = (const float*)d_in[5];
    float* out = (float*)d_out;
    (void)in_sizes; (void)n_in; (void)out_size;

    dim3 grid(Wd / MT, Hh / ROWS, Bb);   // (4, 128, 8)
    nca_mma_kernel<<<grid, NT>>>(x, perc, W1, b1, W2, b2, out);
}